// round 16
// baseline (speedup 1.0000x reference)
#include <cuda_runtime.h>
#include <cuda_fp16.h>
#include <cstdint>

// out = x @ kernel[2]  (seq_len==1 -> softmax over length-1 axis is identity)
// x: [8192,1024] f32, kernel: [3,1024,1024] f32, out: [8192,1024] f32
#define BROWS 8192
#define DDIM  1024

__device__ __half g_xh[BROWS * DDIM];   // 16 MB
__device__ __half g_wh[DDIM * DDIM];    // 2 MB, [K,N] row-major
__device__ int    g_ctr;                // dynamic tile ticket counter

// ------------------------- PTX helpers -------------------------
static __device__ __forceinline__ uint32_t smem_u32(const void* p) {
    uint32_t a;
    asm("{ .reg .u64 t; cvta.to.shared.u64 t, %1; cvt.u32.u64 %0, t; }" : "=r"(a) : "l"(p));
    return a;
}
static __device__ __forceinline__ void cpa16(uint32_t saddr, const void* gptr) {
    asm volatile("cp.async.cg.shared.global [%0], [%1], 16;" :: "r"(saddr), "l"(gptr));
}
static __device__ __forceinline__ void cp_commit() {
    asm volatile("cp.async.commit_group;" ::: "memory");
}
static __device__ __forceinline__ void cp_wait2() {
    asm volatile("cp.async.wait_group 2;" ::: "memory");
}
static __device__ __forceinline__ void cp_wait1() {
    asm volatile("cp.async.wait_group 1;" ::: "memory");
}
static __device__ __forceinline__ void cp_wait0() {
    asm volatile("cp.async.wait_group 0;" ::: "memory");
}
static __device__ __forceinline__ void ldsm4(uint32_t* r, uint32_t a) {
    asm volatile("ldmatrix.sync.aligned.m8n8.x4.shared.b16 {%0,%1,%2,%3}, [%4];"
                 : "=r"(r[0]), "=r"(r[1]), "=r"(r[2]), "=r"(r[3]) : "r"(a));
}
static __device__ __forceinline__ void ldsm4t(uint32_t* r, uint32_t a) {
    asm volatile("ldmatrix.sync.aligned.m8n8.x4.trans.shared.b16 {%0,%1,%2,%3}, [%4];"
                 : "=r"(r[0]), "=r"(r[1]), "=r"(r[2]), "=r"(r[3]) : "r"(a));
}
static __device__ __forceinline__ void mma16816(float* c, const uint32_t* a, const uint32_t* b) {
    asm volatile(
        "mma.sync.aligned.m16n8k16.row.col.f32.f16.f16.f32 "
        "{%0,%1,%2,%3}, {%4,%5,%6,%7}, {%8,%9}, {%0,%1,%2,%3};"
        : "+f"(c[0]), "+f"(c[1]), "+f"(c[2]), "+f"(c[3])
        : "r"(a[0]), "r"(a[1]), "r"(a[2]), "r"(a[3]), "r"(b[0]), "r"(b[1]));
}

// ------------------------- convert kernel (unchanged) -------------------------
__global__ void __launch_bounds__(256) cvt_kernel(const float4* __restrict__ x,
                                                  const float4* __restrict__ w,
                                                  int nx4) {
    if (blockIdx.x == 0 && threadIdx.x == 0) g_ctr = 0;
    int base = blockIdx.x * 1024 + threadIdx.x;
    const float4* src;
    uint2* dst;
    if (base < nx4) {
        src = x;
        dst = (uint2*)g_xh;
    } else {
        src = w - nx4;
        dst = ((uint2*)g_wh) - nx4;
    }
    float4 v[4];
#pragma unroll
    for (int j = 0; j < 4; j++) v[j] = src[base + j * 256];
#pragma unroll
    for (int j = 0; j < 4; j++) {
        __half2 lo = __floats2half2_rn(v[j].x, v[j].y);
        __half2 hi = __floats2half2_rn(v[j].z, v[j].w);
        dst[base + j * 256] = make_uint2(*(uint32_t*)&lo, *(uint32_t*)&hi);
    }
}

// ------------------------- barrier-free per-warp GEMM engines ----------
// 2048 tiles of (64 x 64), BK=32/step, 32 steps/tile. 1 CTA/SM, 256 threads =
// 8 INDEPENDENT warp engines. Each warp: private 3-stage x 8KB cp.async ring
// (A 4KB [64 m-rows x 64B sw] | B 4KB [32 k-rows x 128B sw]), own ticket stream,
// warp tile 64x64 (128 f32 accumulators). ZERO __syncthreads in steady state.
#define WSTAGE     8192
#define N_STAGES   3
#define WARP_SMEM  (N_STAGES * WSTAGE)          // 24576
#define NWARP      8
#define GEMM_SMEM  (NWARP * WARP_SMEM)          // 196608
#define N_TILES    2048                          // 128 (M) x 16 (N)

__global__ void __launch_bounds__(256, 1) gemm_warp_kernel(float* __restrict__ out) {
    extern __shared__ char smem[];
    const int tid  = threadIdx.x;
    const int lane = tid & 31;
    const int wid  = tid >> 5;
    const uint32_t wb = smem_u32(smem) + wid * WARP_SMEM;

    // Per-lane chunk geometry (8 A-chunks + 8 B-chunks of 16B per step).
    uint32_t a_soff[8], b_soff[8];
    int a_goff[8], b_goff[8];
#pragma unroll
    for (int i = 0; i < 8; i++) {
        int idx = lane + i * 32;
        int r = idx >> 2, c = idx & 3;                 // A: 64 rows x 4 chunks
        a_goff[i] = r * DDIM + c * 8;
        a_soff[i] = r * 64 + ((c ^ ((r >> 1) & 3)) * 16);
        int k = idx >> 3, c2 = idx & 7;                // B: 32 k-rows x 8 chunks
        b_goff[i] = k * DDIM + c2 * 8;
        b_soff[i] = 4096 + k * 128 + ((c2 ^ (k & 7)) * 16);
    }

    auto load_step = [&](int m0, int n0, int kt, int s) {
        uint32_t st = wb + s * WSTAGE;
#pragma unroll
        for (int i = 0; i < 8; i++)
            cpa16(st + a_soff[i], g_xh + (size_t)m0 * DDIM + kt * 32 + a_goff[i]);
#pragma unroll
        for (int i = 0; i < 8; i++)
            cpa16(st + b_soff[i], g_wh + (size_t)kt * (32 * DDIM) + n0 + b_goff[i]);
    };

    float c[4][8][4];
#pragma unroll
    for (int i = 0; i < 4; i++)
#pragma unroll
        for (int j = 0; j < 8; j++)
#pragma unroll
            for (int q = 0; q < 4; q++) c[i][j][q] = 0.0f;

    for (;;) {
        int t = 0;
        if (lane == 0) t = atomicAdd(&g_ctr, 1);
        t = __shfl_sync(0xffffffffu, t, 0);
        if (t >= N_TILES) break;
        const int m0 = (t >> 4) * 64;
        const int n0 = (t & 15) * 64;

        // Per-tile prologue: steps 0,1 into stages 0,1.
        load_step(m0, n0, 0, 0);
        cp_commit();
        load_step(m0, n0, 1, 1);
        cp_commit();

#pragma unroll 1
        for (int kt = 0; kt < 32; kt++) {
            // Prefetch step kt+2, then wait for kt's data (per-warp only).
            if (kt < 30) {
                load_step(m0, n0, kt + 2, (kt + 2) % 3);
                cp_commit();
                cp_wait2();
            } else if (kt == 30) {
                cp_wait1();
            } else {
                cp_wait0();
            }
            __syncwarp();

            uint32_t st = wb + (kt % 3) * WSTAGE;
#pragma unroll
            for (int kk = 0; kk < 2; kk++) {
                uint32_t a[4][4], b[4][4];
#pragma unroll
                for (int mt = 0; mt < 4; mt++) {
                    int row = mt * 16 + (lane & 15);
                    int ch  = kk * 2 + (lane >> 4);
                    ldsm4(a[mt], st + row * 64 + ((ch ^ ((row >> 1) & 3)) * 16));
                }
#pragma unroll
                for (int nt = 0; nt < 4; nt++) {
                    int k  = kk * 16 + (lane & 15);
                    int nc = nt * 2 + (lane >> 4);
                    ldsm4t(b[nt], st + 4096 + k * 128 + ((nc ^ (k & 7)) * 16));
                }
#pragma unroll
                for (int mt = 0; mt < 4; mt++)
#pragma unroll
                    for (int nj = 0; nj < 8; nj++)
                        mma16816(c[mt][nj], a[mt], &b[nj >> 1][(nj & 1) * 2]);
            }
        }

        // Epilogue: fire-and-forget STG, then reset accumulators.
#pragma unroll
        for (int mt = 0; mt < 4; mt++) {
#pragma unroll
            for (int nj = 0; nj < 8; nj++) {
                int row = m0 + mt * 16 + (lane >> 2);
                int col = n0 + nj * 8 + (lane & 3) * 2;
                *reinterpret_cast<float2*>(&out[(size_t)row * DDIM + col]) =
                    make_float2(c[mt][nj][0], c[mt][nj][1]);
                *reinterpret_cast<float2*>(&out[(size_t)(row + 8) * DDIM + col]) =
                    make_float2(c[mt][nj][2], c[mt][nj][3]);
                c[mt][nj][0] = 0.0f; c[mt][nj][1] = 0.0f;
                c[mt][nj][2] = 0.0f; c[mt][nj][3] = 0.0f;
            }
        }
    }
    cp_wait0();  // drain before exit
}

// ------------------------- launch -------------------------
extern "C" void kernel_launch(void* const* d_in, const int* in_sizes, int n_in,
                              void* d_out, int out_size) {
    const float* x = (const float*)d_in[0];                 // [8192,1024]
    const float* kern = (const float*)d_in[1];              // [3,1024,1024]
    const float* wv = kern + 2L * DDIM * DDIM;              // kernel[2]: [K,N]
    float* out = (float*)d_out;

    const int nx4 = BROWS * DDIM / 4;   // 2,097,152
    const int nw4 = DDIM * DDIM / 4;    // 262,144
    cvt_kernel<<<(nx4 + nw4) / 1024, 256>>>((const float4*)x, (const float4*)wv, nx4);

    int dev = 0, nsm = 148;
    cudaGetDevice(&dev);
    cudaDeviceGetAttribute(&nsm, cudaDevAttrMultiProcessorCount, dev);
    if (nsm < 1) nsm = 148;

    cudaFuncSetAttribute(gemm_warp_kernel,
                         cudaFuncAttributeMaxDynamicSharedMemorySize, GEMM_SMEM);
    gemm_warp_kernel<<<nsm, 256, GEMM_SMEM>>>(out);
}

// round 17
// speedup vs baseline: 1.0991x; 1.0991x over previous
#include <cuda_runtime.h>
#include <cuda_fp16.h>
#include <cstdint>

// out = x @ kernel[2]  (seq_len==1 -> softmax over length-1 axis is identity)
// x: [8192,1024] f32, kernel: [3,1024,1024] f32, out: [8192,1024] f32
#define BROWS 8192
#define DDIM  1024

__device__ __half g_xh[BROWS * DDIM];   // 16 MB
__device__ __half g_wh[DDIM * DDIM];    // 2 MB, [K,N] row-major
__device__ int    g_ctr;                // dynamic tile ticket counter

// ------------------------- PTX helpers -------------------------
static __device__ __forceinline__ uint32_t smem_u32(const void* p) {
    uint32_t a;
    asm("{ .reg .u64 t; cvta.to.shared.u64 t, %1; cvt.u32.u64 %0, t; }" : "=r"(a) : "l"(p));
    return a;
}
static __device__ __forceinline__ void cpa16(uint32_t saddr, const void* gptr) {
    asm volatile("cp.async.cg.shared.global [%0], [%1], 16;" :: "r"(saddr), "l"(gptr));
}
static __device__ __forceinline__ void cp_commit() {
    asm volatile("cp.async.commit_group;" ::: "memory");
}
static __device__ __forceinline__ void cp_wait2() {
    asm volatile("cp.async.wait_group 2;" ::: "memory");
}
static __device__ __forceinline__ void cp_wait0() {
    asm volatile("cp.async.wait_group 0;" ::: "memory");
}
static __device__ __forceinline__ void ldsm4(uint32_t* r, uint32_t a) {
    asm volatile("ldmatrix.sync.aligned.m8n8.x4.shared.b16 {%0,%1,%2,%3}, [%4];"
                 : "=r"(r[0]), "=r"(r[1]), "=r"(r[2]), "=r"(r[3]) : "r"(a));
}
static __device__ __forceinline__ void ldsm4t(uint32_t* r, uint32_t a) {
    asm volatile("ldmatrix.sync.aligned.m8n8.x4.trans.shared.b16 {%0,%1,%2,%3}, [%4];"
                 : "=r"(r[0]), "=r"(r[1]), "=r"(r[2]), "=r"(r[3]) : "r"(a));
}
static __device__ __forceinline__ void mma16816(float* c, const uint32_t* a, const uint32_t* b) {
    asm volatile(
        "mma.sync.aligned.m16n8k16.row.col.f32.f16.f16.f32 "
        "{%0,%1,%2,%3}, {%4,%5,%6,%7}, {%8,%9}, {%0,%1,%2,%3};"
        : "+f"(c[0]), "+f"(c[1]), "+f"(c[2]), "+f"(c[3])
        : "r"(a[0]), "r"(a[1]), "r"(a[2]), "r"(a[3]), "r"(b[0]), "r"(b[1]));
}

// ------------------------- convert kernel (R10 + PDL trigger) ----------------
__global__ void __launch_bounds__(256) cvt_kernel(const float4* __restrict__ x,
                                                  const float4* __restrict__ w,
                                                  int nx4) {
    if (blockIdx.x == 0 && threadIdx.x == 0) g_ctr = 0;
    int base = blockIdx.x * 1024 + threadIdx.x;
    const float4* src;
    uint2* dst;
    if (base < nx4) {
        src = x;
        dst = (uint2*)g_xh;
    } else {
        src = w - nx4;
        dst = ((uint2*)g_wh) - nx4;
    }
    float4 v[4];
#pragma unroll
    for (int j = 0; j < 4; j++) v[j] = src[base + j * 256];
#pragma unroll
    for (int j = 0; j < 4; j++) {
        __half2 lo = __floats2half2_rn(v[j].x, v[j].y);
        __half2 hi = __floats2half2_rn(v[j].z, v[j].w);
        dst[base + j * 256] = make_uint2(*(uint32_t*)&lo, *(uint32_t*)&hi);
    }
    // PDL: allow the dependent GEMM grid to launch; its griddepcontrol.wait
    // guarantees visibility of all writes above.
    asm volatile("griddepcontrol.launch_dependents;");
}

// ------------------------- persistent dynamic GEMM (R10, + PDL wait) ---------
// 1024 tiles (BM=128 x BN=64), BK=64, 2 CTAs/SM, 256 threads = 8 warps (4x2),
// warp tile 32x32, 4-stage cp.async ring streaming across tile boundaries,
// dynamic tile tickets.
#define ST_B_OFF    16384
#define STAGE_BYTES 24576
#define N_STAGES    4
#define CTRL_OFF    (N_STAGES * STAGE_BYTES)
#define GEMM_SMEM   (CTRL_OFF + 128)            // 98432
#define N_TILES     1024                         // 64 (M) x 16 (N)

__global__ void __launch_bounds__(256, 2) gemm_persist_kernel(float* __restrict__ out) {
    extern __shared__ char smem[];
    const uint32_t sb = smem_u32(smem);
    int* ticket_sm = (int*)(smem + CTRL_OFF);
    const int tid    = threadIdx.x;
    const int lane   = tid & 31;
    const int wid    = tid >> 5;
    const int warp_m = wid >> 1;   // 0..3 -> m offset *32
    const int warp_n = wid & 1;    // 0..1 -> n offset *32

    // Per-thread load geometry (pure arithmetic — done BEFORE the PDL wait so
    // it overlaps the convert kernel's tail).
    int a_goff[4];
    uint32_t a_soff[4];
#pragma unroll
    for (int i = 0; i < 4; i++) {
        int ch = tid + i * 256, r = ch >> 3, c = ch & 7;
        a_goff[i] = r * DDIM + c * 8;
        a_soff[i] = r * 128 + ((c ^ (r & 7)) * 16);
    }
    int b_goff[2];
    uint32_t b_soff[2];
#pragma unroll
    for (int i = 0; i < 2; i++) {
        int ch = tid + i * 256, k = ch >> 3, c = ch & 7;
        b_goff[i] = k * DDIM + c * 8;
        b_soff[i] = ST_B_OFF + k * 128 + ((c ^ (k & 7)) * 16);
    }

    float c[2][4][4];
#pragma unroll
    for (int i = 0; i < 2; i++)
#pragma unroll
        for (int j = 0; j < 4; j++)
#pragma unroll
            for (int q = 0; q < 4; q++) c[i][j][q] = 0.0f;

    // PDL: block until the convert grid's writes (g_xh, g_wh, g_ctr) are visible.
    asm volatile("griddepcontrol.wait;" ::: "memory");

    auto load_step = [&](int by, int bx, int kt, int s) {
        uint32_t st = sb + s * STAGE_BYTES;
#pragma unroll
        for (int i = 0; i < 4; i++)
            cpa16(st + a_soff[i], g_xh + (size_t)by * (128 * DDIM) + kt * 64 + a_goff[i]);
#pragma unroll
        for (int i = 0; i < 2; i++)
            cpa16(st + b_soff[i], g_wh + (size_t)kt * (64 * DDIM) + bx * 64 + b_goff[i]);
    };

    // First ticket.
    if (tid == 0) ticket_sm[0] = atomicAdd(&g_ctr, 1);
    __syncthreads();
    int cur = ticket_sm[0];
    if (cur >= N_TILES) { return; }
    int cur_by = cur >> 4, cur_bx = cur & 15;

    // Prologue: steps 0..2 of first tile into stages 0..2.
#pragma unroll
    for (int p = 0; p < 3; p++) {
        load_step(cur_by, cur_bx, p, p);
        cp_commit();
    }

    int cs = 0;   // compute stage
    int ls = 3;   // load stage
    for (;;) {
        int nxt = N_TILES, nxt_by = 0, nxt_bx = 0;
        for (int kt = 0; kt < 16; kt++) {
            cp_wait2();
            __syncthreads();
            if (kt == 0 && tid == 0) ticket_sm[0] = atomicAdd(&g_ctr, 1);
            if (kt == 12) {
                nxt = ticket_sm[0];       // written at kt==0, 12 barriers ago
                nxt_by = nxt >> 4;
                nxt_bx = nxt & 15;
            }
            // Load step kt+3 (of cur, or first steps of nxt); always commit one group.
            int lkt = kt + 3;
            if (lkt < 16)            load_step(cur_by, cur_bx, lkt, ls);
            else if (nxt < N_TILES)  load_step(nxt_by, nxt_bx, lkt - 16, ls);
            cp_commit();
            ls = (ls + 1) & 3;

            uint32_t st = sb + cs * STAGE_BYTES;
            cs = (cs + 1) & 3;
#pragma unroll
            for (int kk = 0; kk < 4; kk++) {
                uint32_t a[2][4], b[2][4];
#pragma unroll
                for (int mt = 0; mt < 2; mt++) {
                    int row = warp_m * 32 + mt * 16 + (lane & 15);
                    int ch  = kk * 2 + (lane >> 4);
                    ldsm4(a[mt], st + row * 128 + ((ch ^ (row & 7)) * 16));
                }
#pragma unroll
                for (int nt = 0; nt < 2; nt++) {
                    int k  = kk * 16 + (lane & 15);
                    int nc = warp_n * 4 + nt * 2 + (lane >> 4);
                    ldsm4t(b[nt], st + ST_B_OFF + k * 128 + ((nc ^ (k & 7)) * 16));
                }
#pragma unroll
                for (int mt = 0; mt < 2; mt++)
#pragma unroll
                    for (int nj = 0; nj < 4; nj++)
                        mma16816(c[mt][nj], a[mt], &b[nj >> 1][(nj & 1) * 2]);
            }
        }

        // Tile done: store (fire-and-forget, overlaps next tile's MMAs) + reset.
        {
            int cta_m = cur_by * 128;
            int cta_n = cur_bx * 64;
#pragma unroll
            for (int mt = 0; mt < 2; mt++) {
#pragma unroll
                for (int nj = 0; nj < 4; nj++) {
                    int row = cta_m + warp_m * 32 + mt * 16 + (lane >> 2);
                    int col = cta_n + warp_n * 32 + nj * 8 + (lane & 3) * 2;
                    *reinterpret_cast<float2*>(&out[(size_t)row * DDIM + col]) =
                        make_float2(c[mt][nj][0], c[mt][nj][1]);
                    *reinterpret_cast<float2*>(&out[(size_t)(row + 8) * DDIM + col]) =
                        make_float2(c[mt][nj][2], c[mt][nj][3]);
                    c[mt][nj][0] = 0.0f; c[mt][nj][1] = 0.0f;
                    c[mt][nj][2] = 0.0f; c[mt][nj][3] = 0.0f;
                }
            }
        }

        cur = nxt;
        if (cur >= N_TILES) break;
        cur_by = nxt_by;
        cur_bx = nxt_bx;
    }
    cp_wait0();  // drain trailing groups before exit
}

// ------------------------- launch -------------------------
extern "C" void kernel_launch(void* const* d_in, const int* in_sizes, int n_in,
                              void* d_out, int out_size) {
    const float* x = (const float*)d_in[0];                 // [8192,1024]
    const float* kern = (const float*)d_in[1];              // [3,1024,1024]
    const float* wv = kern + 2L * DDIM * DDIM;              // kernel[2]: [K,N]
    float* out = (float*)d_out;

    const int nx4 = BROWS * DDIM / 4;   // 2,097,152
    const int nw4 = DDIM * DDIM / 4;    // 262,144
    cvt_kernel<<<(nx4 + nw4) / 1024, 256>>>((const float4*)x, (const float4*)wv, nx4);

    int dev = 0, nsm = 148;
    cudaGetDevice(&dev);
    cudaDeviceGetAttribute(&nsm, cudaDevAttrMultiProcessorCount, dev);
    int grid = 2 * nsm;
    if (grid < 1 || grid > N_TILES) grid = 296;

    cudaFuncSetAttribute(gemm_persist_kernel,
                         cudaFuncAttributeMaxDynamicSharedMemorySize, GEMM_SMEM);

    // PDL launch: GEMM becomes resident while cvt drains; griddepcontrol.wait
    // inside the kernel provides the data dependency.
    cudaLaunchConfig_t cfg = {};
    cfg.gridDim = dim3(grid, 1, 1);
    cfg.blockDim = dim3(256, 1, 1);
    cfg.dynamicSmemBytes = GEMM_SMEM;
    cfg.stream = 0;
    cudaLaunchAttribute attrs[1];
    attrs[0].id = cudaLaunchAttributeProgrammaticStreamSerialization;
    attrs[0].val.programmaticStreamSerializationAllowed = 1;
    cfg.attrs = attrs;
    cfg.numAttrs = 1;
    cudaError_t e = cudaLaunchKernelEx(&cfg, gemm_persist_kernel, out);
    if (e != cudaSuccess) {
        // Fallback: plain serialized launch (griddepcontrol.wait is a no-op
        // when no programmatic dependency exists).
        gemm_persist_kernel<<<grid, 256, GEMM_SMEM>>>(out);
    }
}